// round 16
// baseline (speedup 1.0000x reference)
#include <cuda_runtime.h>
#include <cuda_bf16.h>
#include <cstdint>
#include <cfloat>

#define NVEC 131072        // 32*64*64 vectors
#define KCB  1024          // codebook entries
#define CDIM 256           // embedding dim
#define HWSZ 4096          // H*W
#define TOTAL_ZQ 33554432  // 32*256*64*64
#define EPS 5e-3f
#define MAXC 32
#define NCHUNK 16          // 16 chunks x 64 codes

// smem layout (bytes). Row stride 264 halves = 528 B (ldmatrix conflict-free).
// B double-buffers OVERLAY the A region (A only needed until fragments are in registers).
#define STRH 264
#define SM_AB   0                         // 67584: A bf16 (prologue) / B bufs (mainloop)
#define BUFB    33792                     // 64*528 per B buffer; buf0 @0, buf1 @33792
#define SM_EN   67584                     // 1024 f32 -> 71680
#define SM_ZN   71680                     // 128 f32  -> 72192
#define SM_MS   72192                     // 128 f32 per-row final min -> 72704
#define SM_D    72704                     // 64 codes x 128 rows x u16 = 16384 -> 89088
#define SM_LIST 89088                     // 128*32 u16 = 8192 -> 97280
#define SM_TOTAL 97280                    // 2 CTAs/SM

// ---------------- device scratch ----------------
__device__ float              g_enorm[KCB];
__device__ float              g_znorm[NVEC];
__device__ __align__(16) __nv_bfloat16 g_cbBf[KCB * CDIM];       // 512 KB
__device__ __align__(16) unsigned short g_dscr[(size_t)NVEC * KCB];  // 256 MB spill
__device__ unsigned long long g_arg[NVEC];
__device__ double             g_loss;

// ---------------- helpers ----------------
__device__ __forceinline__ unsigned long long packkey(float d, int k) {
    unsigned u = __float_as_uint(d);
    u = (u & 0x80000000u) ? ~u : (u | 0x80000000u);
    return ((unsigned long long)u << 32) | (unsigned)k;
}
// order-preserving bf16 u16, rounded toward -inf (safe one-sided for candidate filter)
__device__ __forceinline__ unsigned ord16_down(float s) {
    unsigned u = __float_as_uint(s);
    unsigned h = u >> 16;
    if ((u >> 31) && (u & 0xFFFFu)) h += 1;          // negatives: magnitude up = toward -inf
    return (h & 0x8000u) ? (~h & 0xFFFFu) : (h | 0x8000u);
}
// rounded toward +inf (for the threshold)
__device__ __forceinline__ unsigned ord16_up(float s) {
    unsigned u = __float_as_uint(s);
    unsigned h = u >> 16;
    if (!(u >> 31) && (u & 0xFFFFu)) h += 1;         // positives: magnitude up = toward +inf
    return (h & 0x8000u) ? (~h & 0xFFFFu) : (h | 0x8000u);
}
__device__ __forceinline__ void cp_async16(uint32_t dst, const void* src) {
    asm volatile("cp.async.ca.shared.global [%0], [%1], 16;\n" :: "r"(dst), "l"(src));
}
__device__ __forceinline__ void cp_commit() { asm volatile("cp.async.commit_group;\n"); }
__device__ __forceinline__ void cp_wait0()  { asm volatile("cp.async.wait_group 0;\n"); }
__device__ __forceinline__ void cp_wait1()  { asm volatile("cp.async.wait_group 1;\n"); }
__device__ __forceinline__ void ldsm_x4(uint32_t* r, uint32_t addr) {
    asm volatile("ldmatrix.sync.aligned.m8n8.x4.shared.b16 {%0,%1,%2,%3}, [%4];\n"
                 : "=r"(r[0]), "=r"(r[1]), "=r"(r[2]), "=r"(r[3]) : "r"(addr));
}
__device__ __forceinline__ void mma_bf16(float* d, const uint32_t* a, const uint32_t* b) {
    asm volatile(
        "mma.sync.aligned.m16n8k16.row.col.f32.bf16.bf16.f32 "
        "{%0,%1,%2,%3}, {%4,%5,%6,%7}, {%8,%9}, {%0,%1,%2,%3};\n"
        : "+f"(d[0]), "+f"(d[1]), "+f"(d[2]), "+f"(d[3])
        : "r"(a[0]), "r"(a[1]), "r"(a[2]), "r"(a[3]), "r"(b[0]), "r"(b[1]));
}

// ---------------- kernel 0: ||e_k||^2 + g_loss init ----------------
__global__ void enorm_kernel(const float* __restrict__ cb) {
    int k = blockIdx.x;
    if (k == 0 && threadIdx.x == 0) g_loss = 0.0;
    float v = cb[(size_t)k * CDIM + threadIdx.x];
    float s = v * v;
    #pragma unroll
    for (int o = 16; o; o >>= 1) s += __shfl_xor_sync(0xFFFFFFFFu, s, o);
    __shared__ float ps[8];
    if ((threadIdx.x & 31) == 0) ps[threadIdx.x >> 5] = s;
    __syncthreads();
    if (threadIdx.x == 0) {
        float tot = 0.f;
        #pragma unroll
        for (int i = 0; i < 8; i++) tot += ps[i];
        g_enorm[k] = tot;
    }
}

// ---------------- kernel 1: ||z_n||^2, XLA:CPU chain — VERIFIED, DO NOT TOUCH ----------------
__global__ __launch_bounds__(256)
void znorm_kernel(const float* __restrict__ ze) {
    int n = blockIdx.x * blockDim.x + threadIdx.x;
    if (n >= NVEC) return;
    int b  = n >> 12;
    int hw = n & 4095;
    const float* p = ze + (size_t)b * CDIM * HWSZ + hw;
    float m[8] = {0.f,0.f,0.f,0.f,0.f,0.f,0.f,0.f};
    #pragma unroll 4
    for (int i = 0; i < 32; i++) {
        #pragma unroll
        for (int l = 0; l < 8; l++) {
            float x = p[(size_t)(8 * i + l) * HWSZ];
            m[l] = __fmaf_rn(x, x, m[l]);
        }
    }
    float v0 = __fadd_rn(m[0], m[4]);
    float v1 = __fadd_rn(m[1], m[5]);
    float v2 = __fadd_rn(m[2], m[6]);
    float v3 = __fadd_rn(m[3], m[7]);
    float w0 = __fadd_rn(v0, v2);
    float w1 = __fadd_rn(v1, v3);
    g_znorm[n] = __fadd_rn(w0, w1);
}

// ---------------- kernel 2: convert codebook to bf16 ----------------
__global__ void pack_cb_kernel(const float* __restrict__ cb) {
    int i = blockIdx.x * blockDim.x + threadIdx.x;
    g_cbBf[i] = __float2bfloat16(cb[i]);
}

// ---------------- B-chunk prefetch: 64 codes x 256 k bf16 into padded smem ----------------
__device__ __forceinline__ void prefetch_cb(uint32_t sb, int buf, int chunk, int t) {
    const __nv_bfloat16* src = g_cbBf + (size_t)chunk * 64 * CDIM;
    uint32_t dst = sb + SM_AB + buf * BUFB;
    #pragma unroll
    for (int i = 0; i < 8; i++) {
        int idx = t + 256 * i;               // 0..2047
        int row = idx >> 5, ch = idx & 31;
        cp_async16(dst + row * 528 + ch * 16, src + row * CDIM + ch * 8);
    }
    cp_commit();
}

// exact rescore of one codeword (VERIFIED chain: sequential ascending-c fma)
__device__ __forceinline__ unsigned long long exact_key(
        const float* zcol, float znr, int k, const float* __restrict__ cb) {
    const float* brow = cb + (size_t)k * CDIM;
    float acc = 0.f;
    #pragma unroll 8
    for (int c4 = 0; c4 < 64; c4++) {
        float4 bv = __ldg(reinterpret_cast<const float4*>(brow + c4 * 4));
        acc = __fmaf_rn(zcol[(size_t)(c4 * 4 + 0) * HWSZ], bv.x, acc);
        acc = __fmaf_rn(zcol[(size_t)(c4 * 4 + 1) * HWSZ], bv.y, acc);
        acc = __fmaf_rn(zcol[(size_t)(c4 * 4 + 2) * HWSZ], bv.z, acc);
        acc = __fmaf_rn(zcol[(size_t)(c4 * 4 + 3) * HWSZ], bv.w, acc);
    }
    float t1 = __fadd_rn(znr, g_enorm[k]);
    float d  = __fadd_rn(t1, -__fmul_rn(2.0f, acc));
    return packkey(d, k);
}

// ---------------- kernel 3: single-MMA-pass screen with spill + exact rescore ----------------
__global__ __launch_bounds__(256, 2)
void screen_kernel(const float* __restrict__ ze, const float* __restrict__ cb) {
    extern __shared__ __align__(16) unsigned char smem[];
    const uint32_t sb = (uint32_t)__cvta_generic_to_shared(smem);
    const int t    = threadIdx.x;
    const int lane = t & 31;
    const int w    = t >> 5;
    const int m0   = w * 16;                 // warp's row base
    const int nt   = blockIdx.x;
    const int n0   = nt * 128;
    const int b    = n0 >> 12;
    const int hw0  = n0 & 4095;
    const float* Abase = ze + (size_t)b * CDIM * HWSZ + hw0;

    float* enS = reinterpret_cast<float*>(smem + SM_EN);
    float* znS = reinterpret_cast<float*>(smem + SM_ZN);
    float* mS  = reinterpret_cast<float*>(smem + SM_MS);
    unsigned short* dS    = reinterpret_cast<unsigned short*>(smem + SM_D);
    unsigned short* listS = reinterpret_cast<unsigned short*>(smem + SM_LIST);
    __nv_bfloat16* ABh = reinterpret_cast<__nv_bfloat16*>(smem + SM_AB);

    // -------- prologue: en, zn; A fp32->bf16 into padded smem --------
    #pragma unroll
    for (int i = 0; i < 4; i++) enS[t + 256 * i] = g_enorm[t + 256 * i];
    if (t < 128) znS[t] = g_znorm[n0 + t];

    #pragma unroll 4
    for (int i = 0; i < 32; i++) {
        int f = t + 256 * i;
        int c = f >> 5, r4 = (f & 31) * 4;
        float4 v = *reinterpret_cast<const float4*>(Abase + (size_t)c * HWSZ + r4);
        ABh[(r4 + 0) * STRH + c] = __float2bfloat16(v.x);
        ABh[(r4 + 1) * STRH + c] = __float2bfloat16(v.y);
        ABh[(r4 + 2) * STRH + c] = __float2bfloat16(v.z);
        ABh[(r4 + 3) * STRH + c] = __float2bfloat16(v.w);
    }
    __syncthreads();

    // A fragments: 16 k-steps, register-resident for the whole kernel
    uint32_t afr[16][4];
    #pragma unroll
    for (int ks = 0; ks < 16; ks++) {
        uint32_t addr = sb + SM_AB + (m0 + (lane & 15)) * 528 + ks * 32 + (lane >> 4) * 16;
        ldsm_x4(afr[ks], addr);
    }
    __syncthreads();                          // all fragments read before B overlays A

    prefetch_cb(sb, 0, 0, t);

    const int c0  = (lane & 3) * 2;
    const int rlo = m0 + (lane >> 2);
    const int rhi = rlo + 8;
    float mlo = FLT_MAX, mhi = FLT_MAX;

    // -------- pass 0: ONE MMA pass; s = fl(en - 2S); spill ord16_down(s) --------
    #pragma unroll 1
    for (int chunk = 0; chunk < NCHUNK; chunk++) {
        if (chunk + 1 < NCHUNK) { prefetch_cb(sb, (chunk + 1) & 1, chunk + 1, t); cp_wait1(); }
        else cp_wait0();
        __syncthreads();
        const uint32_t bb = sb + SM_AB + (chunk & 1) * BUFB;
        #pragma unroll
        for (int ntl = 0; ntl < 8; ntl++) {
            float d0[4] = {0.f, 0.f, 0.f, 0.f};
            float d1[4] = {0.f, 0.f, 0.f, 0.f};
            uint32_t baddr = bb + (ntl * 8 + (lane & 7)) * 528 + (lane >> 3) * 16;
            #pragma unroll
            for (int kp = 0; kp < 8; kp++) {
                uint32_t br[4];
                ldsm_x4(br, baddr + kp * 64);
                float* dd = (kp & 1) ? d1 : d0;        // two independent chains
                mma_bf16(dd, afr[2 * kp], br);
                mma_bf16(dd, afr[2 * kp + 1], br + 2);
            }
            int kb = chunk * 64 + ntl * 8 + c0;
            float e0 = enS[kb], e1 = enS[kb + 1];
            float s00 = __fadd_rn(e0, -__fmul_rn(2.f, d0[0] + d1[0]));
            float s01 = __fadd_rn(e1, -__fmul_rn(2.f, d0[1] + d1[1]));
            float s10 = __fadd_rn(e0, -__fmul_rn(2.f, d0[2] + d1[2]));
            float s11 = __fadd_rn(e1, -__fmul_rn(2.f, d0[3] + d1[3]));
            mlo = fminf(mlo, fminf(s00, s01));
            mhi = fminf(mhi, fminf(s10, s11));
            int cl = ntl * 8 + c0;                     // chunk-local code
            dS[(cl    ) * 128 + rlo] = (unsigned short)ord16_down(s00);
            dS[(cl + 1) * 128 + rlo] = (unsigned short)ord16_down(s01);
            dS[(cl    ) * 128 + rhi] = (unsigned short)ord16_down(s10);
            dS[(cl + 1) * 128 + rhi] = (unsigned short)ord16_down(s11);
        }
        __syncthreads();
        // flush 16 KB staging -> global spill (coalesced; visible to block after next barrier)
        {
            uint4* gdst = reinterpret_cast<uint4*>(
                g_dscr + ((size_t)nt * KCB + chunk * 64) * 128);
            const uint4* ssrc = reinterpret_cast<const uint4*>(dS);
            #pragma unroll
            for (int i = 0; i < 4; i++) gdst[t + 256 * i] = ssrc[t + 256 * i];
        }
    }

    // -------- per-row final min --------
    #pragma unroll
    for (int o = 1; o <= 2; o <<= 1) {
        mlo = fminf(mlo, __shfl_xor_sync(0xFFFFFFFFu, mlo, o));
        mhi = fminf(mhi, __shfl_xor_sync(0xFFFFFFFFu, mhi, o));
    }
    if ((lane & 3) == 0) { mS[rlo] = mlo; mS[rhi] = mhi; }
    __syncthreads();

    // -------- pass 1: scan spilled u16s with FINAL threshold (no MMA) --------
    int cnt = 0;
    if (t < 128) {
        const unsigned thr16 = ord16_up(__fadd_rn(mS[t], EPS));
        const unsigned short* dp = g_dscr + ((size_t)nt << 17) + t;   // [k*128 + row]
        #pragma unroll 8
        for (int k = 0; k < KCB; k++) {
            unsigned v = dp[(size_t)k << 7];
            if (v <= thr16) {
                if (cnt < MAXC) listS[t * MAXC + cnt] = (unsigned short)k;
                cnt++;
            }
        }
    }

    // -------- rescore: exact fp32 chain; overflow rows (never in practice) -> FULL scan --------
    if (t < 128) {
        const float znr = znS[t];
        const float* zcol = Abase + t;       // z[c] = zcol[c*HWSZ]
        unsigned long long best = 0xFFFFFFFFFFFFFFFFull;
        if (cnt <= MAXC) {
            for (int ci = 0; ci < cnt; ci++) {
                unsigned long long key = exact_key(zcol, znr, listS[t * MAXC + ci], cb);
                if (key < best) best = key;
            }
        } else {
            for (int k = 0; k < KCB; k++) {
                unsigned long long key = exact_key(zcol, znr, k, cb);
                if (key < best) best = key;
            }
        }
        g_arg[n0 + t] = best;
    }
}

// ---------------- kernel 4: gather z_q, indices, loss — VERIFIED ----------------
__global__ __launch_bounds__(256)
void gather_kernel(const float* __restrict__ ze, const float* __restrict__ cb,
                   float* __restrict__ out) {
    const int nt = blockIdx.x;
    const int n0 = nt * 128;
    const int t  = threadIdx.x;
    const int row = t & 127;
    const int ch  = t >> 7;

    __shared__ int sidx[128];
    if (t < 128) {
        unsigned long long v = g_arg[n0 + t];
        int idx = (int)(unsigned)(v & 0xFFFFFFFFu);
        sidx[t] = idx;
        out[(size_t)TOTAL_ZQ + 1 + n0 + t] = (float)idx;
    }
    __syncthreads();

    const int b = n0 >> 12;
    const int hw0 = n0 & 4095;
    const float* zb = ze  + (size_t)b * CDIM * HWSZ + hw0;
    float*       ob = out + (size_t)b * CDIM * HWSZ + hw0;
    const float* cbr = cb + (size_t)sidx[row] * CDIM;

    float lsum = 0.f;
    for (int c = ch; c < CDIM; c += 2) {
        float q = __ldg(&cbr[c]);
        float z = zb[(size_t)c * HWSZ + row];
        ob[(size_t)c * HWSZ + row] = q;
        float dd = q - z;
        lsum = fmaf(dd, dd, lsum);
    }
    #pragma unroll
    for (int o = 16; o; o >>= 1) lsum += __shfl_xor_sync(0xFFFFFFFFu, lsum, o);
    __shared__ float ps[8];
    if ((t & 31) == 0) ps[t >> 5] = lsum;
    __syncthreads();
    if (t == 0) {
        float s = 0.f;
        #pragma unroll
        for (int i = 0; i < 8; i++) s += ps[i];
        atomicAdd(&g_loss, (double)s);
    }
}

// ---------------- kernel 5: finalize loss ----------------
__global__ void finish_kernel(float* __restrict__ out) {
    out[TOTAL_ZQ] = (float)(1.25 * g_loss / (double)TOTAL_ZQ);
}

// ---------------- launch ----------------
extern "C" void kernel_launch(void* const* d_in, const int* in_sizes, int n_in,
                              void* d_out, int out_size) {
    const float* ze = (const float*)d_in[0];   // (32,256,64,64)
    const float* cb = (const float*)d_in[1];   // (1024,256)
    float* out = (float*)d_out;                // [z_q | loss | indices]

    cudaFuncSetAttribute(screen_kernel,
                         cudaFuncAttributeMaxDynamicSharedMemorySize, SM_TOTAL);

    enorm_kernel<<<KCB, 256>>>(cb);                       // launch 0 (also inits g_loss)
    znorm_kernel<<<NVEC / 256, 256>>>(ze);                // launch 1
    pack_cb_kernel<<<KCB * CDIM / 256, 256>>>(cb);        // launch 2
    screen_kernel<<<NVEC / 128, 256, SM_TOTAL>>>(ze, cb); // launch 3  <- ncu captures idx 3
    gather_kernel<<<1024, 256>>>(ze, cb, out);            // launch 4
    finish_kernel<<<1, 1>>>(out);                         // launch 5
}

// round 17
// speedup vs baseline: 1.0289x; 1.0289x over previous
#include <cuda_runtime.h>
#include <cuda_bf16.h>
#include <cstdint>
#include <cfloat>

#define NVEC 131072        // 32*64*64 vectors
#define KCB  1024          // codebook entries
#define CDIM 256           // embedding dim
#define HWSZ 4096          // H*W
#define TOTAL_ZQ 33554432  // 32*256*64*64
#define SEPS 3.5e-3f       // S-domain margin: covers EPS/2 + en/2 + bf16 screen err
#define MAXC 32
#define NCHUNK 16          // 16 chunks x 64 codes

// smem layout (bytes). Row stride 264 halves = 528 B (ldmatrix conflict-free).
// B double-buffers OVERLAY the A region (A only needed until fragments are in registers).
#define STRH 264
#define SM_AB   0                         // 67584: A bf16 (prologue) / B bufs (mainloop)
#define BUFB    33792                     // 64*528 per B buffer; buf0 @0, buf1 @33792
#define SM_D    67584                     // 32 cp x 136 x u32 = 17408 -> 84992 (pad-136: conflict-free)
#define SM_LIST 84992                     // 128*32 u16 = 8192 -> 93184
#define SM_ZN   93184                     // 128 f32 -> 93696
#define SM_MS   93696                     // 128 f32 per-row S-max -> 94208
#define SM_TOTAL 94208                    // 2 CTAs/SM

// ---------------- device scratch ----------------
__device__ float              g_enorm[KCB];
__device__ float              g_znorm[NVEC];
__device__ __align__(16) __nv_bfloat16 g_cbBf[KCB * CDIM];       // 512 KB
__device__ __align__(16) unsigned g_dscr[(size_t)NVEC * KCB / 2];    // 256 MB spill (u32 = 2 codes)
__device__ unsigned long long g_arg[NVEC];
__device__ double             g_loss;

// ---------------- helpers ----------------
__device__ __forceinline__ unsigned long long packkey(float d, int k) {
    unsigned u = __float_as_uint(d);
    u = (u & 0x80000000u) ? ~u : (u | 0x80000000u);
    return ((unsigned long long)u << 32) | (unsigned)k;
}
// order-preserving 16-bit map of float (monotone increasing), rounded UP in order
__device__ __forceinline__ unsigned ord16_up(float s) {
    unsigned u = __float_as_uint(s);
    unsigned h = u >> 16;
    if (!(u >> 31) && (u & 0xFFFFu)) h += 1;         // toward +inf
    return (h & 0x8000u) ? (~h & 0xFFFFu) : (h | 0x8000u);
}
// rounded DOWN in order
__device__ __forceinline__ unsigned ord16_down(float s) {
    unsigned u = __float_as_uint(s);
    unsigned h = u >> 16;
    if ((u >> 31) && (u & 0xFFFFu)) h += 1;          // toward -inf
    return (h & 0x8000u) ? (~h & 0xFFFFu) : (h | 0x8000u);
}
__device__ __forceinline__ void cp_async16(uint32_t dst, const void* src) {
    asm volatile("cp.async.ca.shared.global [%0], [%1], 16;\n" :: "r"(dst), "l"(src));
}
__device__ __forceinline__ void cp_commit() { asm volatile("cp.async.commit_group;\n"); }
__device__ __forceinline__ void cp_wait0()  { asm volatile("cp.async.wait_group 0;\n"); }
__device__ __forceinline__ void cp_wait1()  { asm volatile("cp.async.wait_group 1;\n"); }
__device__ __forceinline__ void ldsm_x4(uint32_t* r, uint32_t addr) {
    asm volatile("ldmatrix.sync.aligned.m8n8.x4.shared.b16 {%0,%1,%2,%3}, [%4];\n"
                 : "=r"(r[0]), "=r"(r[1]), "=r"(r[2]), "=r"(r[3]) : "r"(addr));
}
__device__ __forceinline__ void mma_bf16(float* d, const uint32_t* a, const uint32_t* b) {
    asm volatile(
        "mma.sync.aligned.m16n8k16.row.col.f32.bf16.bf16.f32 "
        "{%0,%1,%2,%3}, {%4,%5,%6,%7}, {%8,%9}, {%0,%1,%2,%3};\n"
        : "+f"(d[0]), "+f"(d[1]), "+f"(d[2]), "+f"(d[3])
        : "r"(a[0]), "r"(a[1]), "r"(a[2]), "r"(a[3]), "r"(b[0]), "r"(b[1]));
}

// ---------------- kernel 0: ||e_k||^2 + g_loss init ----------------
__global__ void enorm_kernel(const float* __restrict__ cb) {
    int k = blockIdx.x;
    if (k == 0 && threadIdx.x == 0) g_loss = 0.0;
    float v = cb[(size_t)k * CDIM + threadIdx.x];
    float s = v * v;
    #pragma unroll
    for (int o = 16; o; o >>= 1) s += __shfl_xor_sync(0xFFFFFFFFu, s, o);
    __shared__ float ps[8];
    if ((threadIdx.x & 31) == 0) ps[threadIdx.x >> 5] = s;
    __syncthreads();
    if (threadIdx.x == 0) {
        float tot = 0.f;
        #pragma unroll
        for (int i = 0; i < 8; i++) tot += ps[i];
        g_enorm[k] = tot;
    }
}

// ---------------- kernel 1: ||z_n||^2, XLA:CPU chain — VERIFIED, DO NOT TOUCH ----------------
__global__ __launch_bounds__(256)
void znorm_kernel(const float* __restrict__ ze) {
    int n = blockIdx.x * blockDim.x + threadIdx.x;
    if (n >= NVEC) return;
    int b  = n >> 12;
    int hw = n & 4095;
    const float* p = ze + (size_t)b * CDIM * HWSZ + hw;
    float m[8] = {0.f,0.f,0.f,0.f,0.f,0.f,0.f,0.f};
    #pragma unroll 4
    for (int i = 0; i < 32; i++) {
        #pragma unroll
        for (int l = 0; l < 8; l++) {
            float x = p[(size_t)(8 * i + l) * HWSZ];
            m[l] = __fmaf_rn(x, x, m[l]);
        }
    }
    float v0 = __fadd_rn(m[0], m[4]);
    float v1 = __fadd_rn(m[1], m[5]);
    float v2 = __fadd_rn(m[2], m[6]);
    float v3 = __fadd_rn(m[3], m[7]);
    float w0 = __fadd_rn(v0, v2);
    float w1 = __fadd_rn(v1, v3);
    g_znorm[n] = __fadd_rn(w0, w1);
}

// ---------------- kernel 2: convert codebook to bf16 ----------------
__global__ void pack_cb_kernel(const float* __restrict__ cb) {
    int i = blockIdx.x * blockDim.x + threadIdx.x;
    g_cbBf[i] = __float2bfloat16(cb[i]);
}

// ---------------- B-chunk prefetch: 64 codes x 256 k bf16 into padded smem ----------------
__device__ __forceinline__ void prefetch_cb(uint32_t sb, int buf, int chunk, int t) {
    const __nv_bfloat16* src = g_cbBf + (size_t)chunk * 64 * CDIM;
    uint32_t dst = sb + SM_AB + buf * BUFB;
    #pragma unroll
    for (int i = 0; i < 8; i++) {
        int idx = t + 256 * i;               // 0..2047
        int row = idx >> 5, ch = idx & 31;
        cp_async16(dst + row * 528 + ch * 16, src + row * CDIM + ch * 8);
    }
    cp_commit();
}

// exact rescore of one codeword (VERIFIED chain: sequential ascending-c fma)
__device__ __forceinline__ unsigned long long exact_key(
        const float* zcol, float znr, int k, const float* __restrict__ cb) {
    const float* brow = cb + (size_t)k * CDIM;
    float acc = 0.f;
    #pragma unroll 8
    for (int c4 = 0; c4 < 64; c4++) {
        float4 bv = __ldg(reinterpret_cast<const float4*>(brow + c4 * 4));
        acc = __fmaf_rn(zcol[(size_t)(c4 * 4 + 0) * HWSZ], bv.x, acc);
        acc = __fmaf_rn(zcol[(size_t)(c4 * 4 + 1) * HWSZ], bv.y, acc);
        acc = __fmaf_rn(zcol[(size_t)(c4 * 4 + 2) * HWSZ], bv.z, acc);
        acc = __fmaf_rn(zcol[(size_t)(c4 * 4 + 3) * HWSZ], bv.w, acc);
    }
    float t1 = __fadd_rn(znr, g_enorm[k]);
    float d  = __fadd_rn(t1, -__fmul_rn(2.0f, acc));
    return packkey(d, k);
}

// ---------------- kernel 3: single-pass S-max screen with packed spill + exact rescore ----------------
__global__ __launch_bounds__(256, 2)
void screen_kernel(const float* __restrict__ ze, const float* __restrict__ cb) {
    extern __shared__ __align__(16) unsigned char smem[];
    const uint32_t sb = (uint32_t)__cvta_generic_to_shared(smem);
    const int t    = threadIdx.x;
    const int lane = t & 31;
    const int w    = t >> 5;
    const int m0   = w * 16;                 // warp's row base
    const int nt   = blockIdx.x;
    const int n0   = nt * 128;
    const int b    = n0 >> 12;
    const int hw0  = n0 & 4095;
    const float* Abase = ze + (size_t)b * CDIM * HWSZ + hw0;

    float* znS = reinterpret_cast<float*>(smem + SM_ZN);
    float* mS  = reinterpret_cast<float*>(smem + SM_MS);
    unsigned* dS32 = reinterpret_cast<unsigned*>(smem + SM_D);
    unsigned short* listS = reinterpret_cast<unsigned short*>(smem + SM_LIST);
    __nv_bfloat16* ABh = reinterpret_cast<__nv_bfloat16*>(smem + SM_AB);

    // -------- prologue: zn; A fp32->bf16 into padded smem --------
    if (t < 128) znS[t] = g_znorm[n0 + t];

    #pragma unroll 4
    for (int i = 0; i < 32; i++) {
        int f = t + 256 * i;
        int c = f >> 5, r4 = (f & 31) * 4;
        float4 v = *reinterpret_cast<const float4*>(Abase + (size_t)c * HWSZ + r4);
        ABh[(r4 + 0) * STRH + c] = __float2bfloat16(v.x);
        ABh[(r4 + 1) * STRH + c] = __float2bfloat16(v.y);
        ABh[(r4 + 2) * STRH + c] = __float2bfloat16(v.z);
        ABh[(r4 + 3) * STRH + c] = __float2bfloat16(v.w);
    }
    __syncthreads();

    // A fragments: 16 k-steps, register-resident for the whole kernel
    uint32_t afr[16][4];
    #pragma unroll
    for (int ks = 0; ks < 16; ks++) {
        uint32_t addr = sb + SM_AB + (m0 + (lane & 15)) * 528 + ks * 32 + (lane >> 4) * 16;
        ldsm_x4(afr[ks], addr);
    }
    __syncthreads();                          // all fragments read before B overlays A

    prefetch_cb(sb, 0, 0, t);

    const int cpl = lane & 3;                 // code-pair slot within ntl
    const int rlo = m0 + (lane >> 2);
    const int rhi = rlo + 8;
    float mlo = -FLT_MAX, mhi = -FLT_MAX;     // track per-row MAX of S

    // -------- pass 0: ONE MMA pass; spill ord16_up(S); track per-row max --------
    #pragma unroll 1
    for (int chunk = 0; chunk < NCHUNK; chunk++) {
        if (chunk + 1 < NCHUNK) { prefetch_cb(sb, (chunk + 1) & 1, chunk + 1, t); cp_wait1(); }
        else cp_wait0();
        __syncthreads();
        const uint32_t bb = sb + SM_AB + (chunk & 1) * BUFB;
        #pragma unroll
        for (int ntl = 0; ntl < 8; ntl++) {
            float d[4][4];
            #pragma unroll
            for (int j = 0; j < 4; j++)
                #pragma unroll
                for (int q = 0; q < 4; q++) d[j][q] = 0.f;
            uint32_t baddr = bb + (ntl * 8 + (lane & 7)) * 528 + (lane >> 3) * 16;
            #pragma unroll
            for (int kp = 0; kp < 8; kp++) {
                uint32_t br[4];
                ldsm_x4(br, baddr + kp * 64);
                mma_bf16(d[(2 * kp) & 3],     afr[2 * kp],     br);      // 4 indep chains
                mma_bf16(d[(2 * kp + 1) & 3], afr[2 * kp + 1], br + 2);
            }
            float S00 = __fadd_rn(__fadd_rn(d[0][0], d[1][0]), __fadd_rn(d[2][0], d[3][0]));
            float S01 = __fadd_rn(__fadd_rn(d[0][1], d[1][1]), __fadd_rn(d[2][1], d[3][1]));
            float S10 = __fadd_rn(__fadd_rn(d[0][2], d[1][2]), __fadd_rn(d[2][2], d[3][2]));
            float S11 = __fadd_rn(__fadd_rn(d[0][3], d[1][3]), __fadd_rn(d[2][3], d[3][3]));
            mlo = fmaxf(mlo, fmaxf(S00, S01));
            mhi = fmaxf(mhi, fmaxf(S10, S11));
            unsigned plo = ord16_up(S00) | (ord16_up(S01) << 16);
            unsigned phi = ord16_up(S10) | (ord16_up(S11) << 16);
            int cp = ntl * 4 + cpl;           // code pair 0..31 within chunk
            dS32[cp * 136 + rlo] = plo;       // stride 136: conflict-free
            dS32[cp * 136 + rhi] = phi;
        }
        __syncthreads();
        // flush 16 KB staging -> global spill, coalesced, compact [cp][row] u32
        {
            unsigned* gdst = g_dscr + ((size_t)nt * NCHUNK + chunk) * 32 * 128;
            #pragma unroll
            for (int i = 0; i < 16; i++) {
                int idx = t + 256 * i;        // 0..4095
                int cp = idx >> 7, row = idx & 127;
                gdst[cp * 128 + row] = dS32[cp * 136 + row];
            }
        }
    }

    // -------- per-row final S-max --------
    #pragma unroll
    for (int o = 1; o <= 2; o <<= 1) {
        mlo = fmaxf(mlo, __shfl_xor_sync(0xFFFFFFFFu, mlo, o));
        mhi = fmaxf(mhi, __shfl_xor_sync(0xFFFFFFFFu, mhi, o));
    }
    if ((lane & 3) == 0) { mS[rlo] = mlo; mS[rhi] = mhi; }
    __syncthreads();

    // -------- pass 1: scan spilled u32s with FINAL threshold (no MMA) --------
    int cnt = 0;
    if (t < 128) {
        const unsigned thr16 = ord16_down(__fadd_rn(mS[t], -SEPS));
        const unsigned* dp32 = g_dscr + ((size_t)nt << 16) + t;   // [kk*128 + row]
        #pragma unroll 8
        for (int kk = 0; kk < 512; kk++) {
            unsigned v = dp32[(size_t)kk << 7];
            unsigned lo = v & 0xFFFFu, hi = v >> 16;
            if (lo >= thr16) { if (cnt < MAXC) listS[t * MAXC + cnt] = (unsigned short)(2 * kk);     cnt++; }
            if (hi >= thr16) { if (cnt < MAXC) listS[t * MAXC + cnt] = (unsigned short)(2 * kk + 1); cnt++; }
        }
    }

    // -------- rescore: exact fp32 chain; overflow rows -> FULL exact scan --------
    if (t < 128) {
        const float znr = znS[t];
        const float* zcol = Abase + t;       // z[c] = zcol[c*HWSZ]
        unsigned long long best = 0xFFFFFFFFFFFFFFFFull;
        if (cnt <= MAXC) {
            for (int ci = 0; ci < cnt; ci++) {
                unsigned long long key = exact_key(zcol, znr, listS[t * MAXC + ci], cb);
                if (key < best) best = key;
            }
        } else {
            for (int k = 0; k < KCB; k++) {
                unsigned long long key = exact_key(zcol, znr, k, cb);
                if (key < best) best = key;
            }
        }
        g_arg[n0 + t] = best;
    }
}

// ---------------- kernel 4: gather z_q, indices, loss — VERIFIED ----------------
__global__ __launch_bounds__(256)
void gather_kernel(const float* __restrict__ ze, const float* __restrict__ cb,
                   float* __restrict__ out) {
    const int nt = blockIdx.x;
    const int n0 = nt * 128;
    const int t  = threadIdx.x;
    const int row = t & 127;
    const int ch  = t >> 7;

    __shared__ int sidx[128];
    if (t < 128) {
        unsigned long long v = g_arg[n0 + t];
        int idx = (int)(unsigned)(v & 0xFFFFFFFFu);
        sidx[t] = idx;
        out[(size_t)TOTAL_ZQ + 1 + n0 + t] = (float)idx;
    }
    __syncthreads();

    const int b = n0 >> 12;
    const int hw0 = n0 & 4095;
    const float* zb = ze  + (size_t)b * CDIM * HWSZ + hw0;
    float*       ob = out + (size_t)b * CDIM * HWSZ + hw0;
    const float* cbr = cb + (size_t)sidx[row] * CDIM;

    float lsum = 0.f;
    for (int c = ch; c < CDIM; c += 2) {
        float q = __ldg(&cbr[c]);
        float z = zb[(size_t)c * HWSZ + row];
        ob[(size_t)c * HWSZ + row] = q;
        float dd = q - z;
        lsum = fmaf(dd, dd, lsum);
    }
    #pragma unroll
    for (int o = 16; o; o >>= 1) lsum += __shfl_xor_sync(0xFFFFFFFFu, lsum, o);
    __shared__ float ps[8];
    if ((t & 31) == 0) ps[t >> 5] = lsum;
    __syncthreads();
    if (t == 0) {
        float s = 0.f;
        #pragma unroll
        for (int i = 0; i < 8; i++) s += ps[i];
        atomicAdd(&g_loss, (double)s);
    }
}

// ---------------- kernel 5: finalize loss ----------------
__global__ void finish_kernel(float* __restrict__ out) {
    out[TOTAL_ZQ] = (float)(1.25 * g_loss / (double)TOTAL_ZQ);
}

// ---------------- launch ----------------
extern "C" void kernel_launch(void* const* d_in, const int* in_sizes, int n_in,
                              void* d_out, int out_size) {
    const float* ze = (const float*)d_in[0];   // (32,256,64,64)
    const float* cb = (const float*)d_in[1];   // (1024,256)
    float* out = (float*)d_out;                // [z_q | loss | indices]

    cudaFuncSetAttribute(screen_kernel,
                         cudaFuncAttributeMaxDynamicSharedMemorySize, SM_TOTAL);

    enorm_kernel<<<KCB, 256>>>(cb);                       // launch 0 (also inits g_loss)
    znorm_kernel<<<NVEC / 256, 256>>>(ze);                // launch 1
    pack_cb_kernel<<<KCB * CDIM / 256, 256>>>(cb);        // launch 2
    screen_kernel<<<NVEC / 128, 256, SM_TOTAL>>>(ze, cb); // launch 3  <- ncu captures idx 3
    gather_kernel<<<1024, 256>>>(ze, cb, out);            // launch 4
    finish_kernel<<<1, 1>>>(out);                         // launch 5
}